// round 4
// baseline (speedup 1.0000x reference)
#include <cuda_runtime.h>
#include <math.h>

// Problem constants (fixed shapes from reference)
#define BB 8
#define NN 256
#define DD 128
#define NE (BB*NN*NN)          // 524288 edges
#define ROWS (BB*NN)           // 2048
#define TI 4                   // rows per mega-block
#define NB (ROWS/TI)           // 512 mega-blocks
#define BN_EPS 1e-5f

// Scratch (static __device__ — no allocation)
__device__ float g_x[ROWS*DD];       // pre-BN linear+relu output (1 MB)
__device__ float g_psum[DD*NB];      // per-block BN partial sums (channel-major)
__device__ float g_psq[DD*NB];       // per-block BN partial sum-of-squares
__device__ float g_scale[DD];        // folded BN scale
__device__ float g_shift[DD];        // folded BN shift

// ---------------------------------------------------------------------------
// MEGA kernel: one block = TI=4 consecutive rows (same batch).
//   Phase A: stream e -> out_e (streaming hints) + per-edge L2 norms -> smem
//   Phase B: per-row softmax over 256 norms (1 warp / row)
//   Phase C: agg[r,d] = sum_j p[r,j]*h[b,j,d]  (j split across thread halves)
//   Phase D: y = relu((h+agg) @ W^T + bias) -> g_x + BN partials
// 256 threads. Compute hides under the 512 KB/block memory stream.
// ---------------------------------------------------------------------------
__global__ void __launch_bounds__(256) k_mega(
    const float4* __restrict__ e4, float4* __restrict__ oute4,
    const float* __restrict__ h, const float* __restrict__ W,
    const float* __restrict__ bias)
{
    __shared__ float sp [TI * NN];        // 4 KB: norms -> softmax probs
    __shared__ float sagg[2 * TI * DD];   // 4 KB: agg halves
    __shared__ float ss [TI * DD];        // 2 KB: h + agg
    __shared__ float sy [2 * TI * DD];    // 4 KB: linear halves

    const int t    = threadIdx.x;         // 0..255
    const int w    = t >> 5;              // warp 0..7
    const int lane = t & 31;
    const int blk  = blockIdx.x;          // 0..511
    const int gi0  = blk * TI;            // first global row
    const int b    = gi0 >> 8;            // batch (TI divides NN)
    const int i0   = gi0 & (NN - 1);      // local row within batch

    // ---------------- Phase A: stream + norms ----------------
    // Block's edges: E0 .. E0+1023 (4 rows x 256). Warp w handles 128 edges.
    const size_t E0 = (size_t)gi0 * NN;
#pragma unroll 1
    for (int bi = 0; bi < 16; bi++) {
        const int    le0   = w * 128 + bi * 8;       // local edge of this batch
        const size_t edge0 = E0 + le0;

        float4 v[8];
#pragma unroll
        for (int k = 0; k < 8; k++)
            v[k] = __ldcs(&e4[(edge0 + k) * 32 + lane]);   // MLP=8
#pragma unroll
        for (int k = 0; k < 8; k++)
            __stcs(&oute4[(edge0 + k) * 32 + lane], v[k]);

        float s[8];
#pragma unroll
        for (int k = 0; k < 8; k++) {
            s[k] = v[k].x*v[k].x + v[k].y*v[k].y + v[k].z*v[k].z + v[k].w*v[k].w;
#pragma unroll
            for (int o = 16; o; o >>= 1)
                s[k] += __shfl_xor_sync(0xffffffffu, s[k], o);
        }
        float mine = s[0];
#pragma unroll
        for (int k = 1; k < 8; k++)
            mine = (lane == k) ? s[k] : mine;
        if (lane < 8)
            sp[le0 + lane] = sqrtf(mine);
    }
    __syncthreads();

    // ---------------- Phase B: softmax (warp r handles row r) ----------------
    if (w < TI) {
        const int r = w;
        float v[8];
        float m = -1e30f;
#pragma unroll
        for (int q = 0; q < 8; q++) {
            v[q] = sp[r * NN + lane + 32 * q];
            m = fmaxf(m, v[q]);
        }
#pragma unroll
        for (int o = 16; o; o >>= 1)
            m = fmaxf(m, __shfl_xor_sync(0xffffffffu, m, o));
        float sum = 0.f;
#pragma unroll
        for (int q = 0; q < 8; q++) { v[q] = __expf(v[q] - m); sum += v[q]; }
#pragma unroll
        for (int o = 16; o; o >>= 1)
            sum += __shfl_xor_sync(0xffffffffu, sum, o);
        const float inv = 1.0f / sum;
#pragma unroll
        for (int q = 0; q < 8; q++)
            sp[r * NN + lane + 32 * q] = v[q] * inv;
    }
    __syncthreads();

    // ---------------- Phase C: aggregation ----------------
    // thread t: channel d = t&127, j-half = t>>7
    const int d    = t & (DD - 1);
    const int half = t >> 7;
    const float* hb = h + (size_t)b * NN * DD;

    {
        float acc[TI];
#pragma unroll
        for (int r = 0; r < TI; r++) acc[r] = 0.f;

        const int j0 = half * (NN / 2);
        for (int j = j0; j < j0 + NN / 2; j += 4) {
            const float hv0 = hb[(j + 0) * DD + d];
            const float hv1 = hb[(j + 1) * DD + d];
            const float hv2 = hb[(j + 2) * DD + d];
            const float hv3 = hb[(j + 3) * DD + d];
#pragma unroll
            for (int r = 0; r < TI; r++) {
                const float4 p = *(const float4*)&sp[r * NN + j];  // smem bcast
                acc[r] += p.x * hv0 + p.y * hv1 + p.z * hv2 + p.w * hv3;
            }
        }
#pragma unroll
        for (int r = 0; r < TI; r++)
            sagg[half * (TI * DD) + r * DD + d] = acc[r];
    }
    __syncthreads();

    // combine halves + add h  (threads t<128)
    if (t < DD) {
#pragma unroll
        for (int r = 0; r < TI; r++)
            ss[r * DD + t] = sagg[r * DD + t] + sagg[TI * DD + r * DD + t]
                           + hb[(i0 + r) * DD + t];
    }
    __syncthreads();

    // ---------------- Phase D: linear + ReLU + BN partials ----------------
    // thread t: output channel k = t&127, d-half = t>>7
    {
        const int k = d;            // alias
        float y[TI];
#pragma unroll
        for (int r = 0; r < TI; r++) y[r] = 0.f;

        const float* wrow = W + (size_t)k * DD + half * (DD / 2);
        const float* sbase = ss + half * (DD / 2);
        for (int dd = 0; dd < DD / 2; dd += 4) {
            const float4 wv = *(const float4*)&wrow[dd];
#pragma unroll
            for (int r = 0; r < TI; r++) {
                const float4 sv = *(const float4*)&sbase[r * DD + dd]; // bcast
                y[r] += sv.x * wv.x + sv.y * wv.y + sv.z * wv.z + sv.w * wv.w;
            }
        }
#pragma unroll
        for (int r = 0; r < TI; r++)
            sy[half * (TI * DD) + r * DD + k] = y[r];
    }
    __syncthreads();

    if (t < DD) {
        const float bk = bias[t];
        float ps = 0.f, pq = 0.f;
#pragma unroll
        for (int r = 0; r < TI; r++) {
            const float v = fmaxf(sy[r * DD + t] + sy[TI * DD + r * DD + t] + bk, 0.f);
            g_x[(size_t)(gi0 + r) * DD + t] = v;
            ps += v;
            pq += v * v;
        }
        g_psum[t * NB + blk] = ps;
        g_psq [t * NB + blk] = pq;
    }
}

// ---------------------------------------------------------------------------
// K3: one block per channel; 256 threads reduce the 512 block partials
// (coalesced, channel-major), fold gamma/beta/mean/istd into scale+shift.
// ---------------------------------------------------------------------------
__global__ void __launch_bounds__(256) k3_bn_stats(
    const float* __restrict__ gamma, const float* __restrict__ beta)
{
    __shared__ float shs[256], shq[256];
    const int c = blockIdx.x;            // channel 0..127
    const int t = threadIdx.x;           // 0..255
    shs[t] = g_psum[c * NB + t] + g_psum[c * NB + t + 256];
    shq[t] = g_psq [c * NB + t] + g_psq [c * NB + t + 256];
    __syncthreads();
#pragma unroll
    for (int o = 128; o; o >>= 1) {
        if (t < o) { shs[t] += shs[t + o]; shq[t] += shq[t + o]; }
        __syncthreads();
    }
    if (t == 0) {
        const float inv_n = 1.0f / (float)ROWS;
        const float mean = shs[0] * inv_n;
        const float var  = shq[0] * inv_n - mean * mean;   // biased variance
        const float istd = rsqrtf(var + BN_EPS);
        const float sc   = gamma[c] * istd;
        g_scale[c] = sc;
        g_shift[c] = beta[c] - mean * sc;
    }
}

// ---------------------------------------------------------------------------
// K4: out_h = g_x * scale + shift + h   (float4, 65536 vec-elements)
// ---------------------------------------------------------------------------
__global__ void __launch_bounds__(256) k4_finalize(
    const float4* __restrict__ h4, float4* __restrict__ out4)
{
    const int i = blockIdx.x * blockDim.x + threadIdx.x;   // 0..65535
    const float4 x  = ((const float4*)g_x)[i];
    const float4 hv = h4[i];
    const int c = (i * 4) & (DD - 1);
    const float4 sc = *(const float4*)&g_scale[c];
    const float4 sh = *(const float4*)&g_shift[c];
    float4 o;
    o.x = x.x * sc.x + sh.x + hv.x;
    o.y = x.y * sc.y + sh.y + hv.y;
    o.z = x.z * sc.z + sh.z + hv.z;
    o.w = x.w * sc.w + sh.w + hv.w;
    out4[i] = o;
}

// ---------------------------------------------------------------------------
// Launch. Inputs (metadata order): h, e, W, b, gamma, beta.
// Output: [h_new (2048*128 f32)] ++ [e (8*256*256*128 f32)].
// ---------------------------------------------------------------------------
extern "C" void kernel_launch(void* const* d_in, const int* in_sizes, int n_in,
                              void* d_out, int out_size)
{
    const float* h     = (const float*)d_in[0];
    const float* e     = (const float*)d_in[1];
    const float* W     = (const float*)d_in[2];
    const float* bias  = (const float*)d_in[3];
    const float* gamma = (const float*)d_in[4];
    const float* beta  = (const float*)d_in[5];

    float* out_e = (float*)d_out + (size_t)ROWS * DD;

    // MEGA: 512 blocks x 256 threads — stream + norms + softmax + agg + linear
    k_mega<<<NB, 256>>>((const float4*)e, (float4*)out_e, h, W, bias);

    // K3: one block per channel
    k3_bn_stats<<<DD, 256>>>(gamma, beta);

    // K4: 65536 float4 / 256 = 256 blocks
    k4_finalize<<<ROWS * DD / 4 / 256, 256>>>((const float4*)h, (float4*)d_out);
}

// round 5
// speedup vs baseline: 1.1337x; 1.1337x over previous
#include <cuda_runtime.h>
#include <math.h>

// Problem constants (fixed shapes from reference)
#define BB 8
#define NN 256
#define DD 128
#define NE (BB*NN*NN)          // 524288 edges
#define ROWS (BB*NN)           // 2048
#define TI 4                   // rows per K2 block
#define NB (ROWS/TI)           // 512 K2 blocks
#define BN_EPS 1e-5f

// Scratch (static __device__ — no allocation)
__device__ float g_w[NE];            // edge softmax weights (2 MB)
__device__ float g_x[ROWS*DD];       // pre-BN linear+relu output (1 MB)
__device__ float g_psum[DD*NB];      // per-block BN partial sums (channel-major)
__device__ float g_psq[DD*NB];       // per-block BN partial sum-of-squares
__device__ float g_scale[DD];        // folded BN scale
__device__ float g_shift[DD];        // folded BN shift

// ---------------------------------------------------------------------------
// K1 (UNCHANGED from R3 — measured ~5.6 TB/s): per-edge L2 norm + passthrough
// copy of e. One warp = 8 edges, streaming hints, coalesced 32B norm writes.
// Memory-only kernel: nothing competes with the stream.
// ---------------------------------------------------------------------------
__global__ void __launch_bounds__(256) k1_norm_copy(
    const float4* __restrict__ e4, float4* __restrict__ oute4)
{
    const int warp  = (blockIdx.x * blockDim.x + threadIdx.x) >> 5;
    const int lane  = threadIdx.x & 31;
    const size_t edge0 = (size_t)warp * 8;          // 8 edges per warp

    float4 v[8];
#pragma unroll
    for (int k = 0; k < 8; k++)
        v[k] = __ldcs(&e4[(edge0 + k) * 32 + lane]);   // front-batched MLP=8
#pragma unroll
    for (int k = 0; k < 8; k++)
        __stcs(&oute4[(edge0 + k) * 32 + lane], v[k]);

    float s[8];
#pragma unroll
    for (int k = 0; k < 8; k++) {
        s[k] = v[k].x*v[k].x + v[k].y*v[k].y + v[k].z*v[k].z + v[k].w*v[k].w;
#pragma unroll
        for (int o = 16; o; o >>= 1)
            s[k] += __shfl_xor_sync(0xffffffffu, s[k], o);
    }
    float mine = s[0];
#pragma unroll
    for (int k = 1; k < 8; k++)
        mine = (lane == k) ? s[k] : mine;
    if (lane < 8)
        g_w[edge0 + lane] = sqrtf(mine);
}

// ---------------------------------------------------------------------------
// K2: softmax + aggregation + linear, high-parallelism version.
// 512 blocks x 256 threads, TI=4 rows per block.
//   softmax: warp r handles row r (warps 0..3)
//   agg:     thread = (channel d = t&127, j-half = t>>7)
//   linear:  thread = (out channel k = t&127, d-half = t>>7)
// ---------------------------------------------------------------------------
__global__ void __launch_bounds__(256) k2_agg_linear(
    const float* __restrict__ h, const float* __restrict__ W,
    const float* __restrict__ bias)
{
    __shared__ float sp [TI * NN];        // 4 KB: softmax probs
    __shared__ float sagg[2 * TI * DD];   // 4 KB: agg halves
    __shared__ float ss [TI * DD];        // 2 KB: h + agg
    __shared__ float sy [2 * TI * DD];    // 4 KB: linear halves

    const int t    = threadIdx.x;         // 0..255
    const int w    = t >> 5;              // warp 0..7
    const int lane = t & 31;
    const int blk  = blockIdx.x;          // 0..511
    const int gi0  = blk * TI;            // first global row
    const int b    = gi0 >> 8;            // batch
    const int i0   = gi0 & (NN - 1);      // local row within batch

    // Load 4 rows x 256 weights (coalesced: 1024 floats)
    const float* wsrc = g_w + (size_t)gi0 * NN;
#pragma unroll
    for (int k = 0; k < TI * NN / 256; k++)
        sp[t + 256 * k] = wsrc[t + 256 * k];
    __syncthreads();

    // Softmax: warp r handles row r
    if (w < TI) {
        const int r = w;
        float v[8];
        float m = -1e30f;
#pragma unroll
        for (int q = 0; q < 8; q++) {
            v[q] = sp[r * NN + lane + 32 * q];
            m = fmaxf(m, v[q]);
        }
#pragma unroll
        for (int o = 16; o; o >>= 1)
            m = fmaxf(m, __shfl_xor_sync(0xffffffffu, m, o));
        float sum = 0.f;
#pragma unroll
        for (int q = 0; q < 8; q++) { v[q] = __expf(v[q] - m); sum += v[q]; }
#pragma unroll
        for (int o = 16; o; o >>= 1)
            sum += __shfl_xor_sync(0xffffffffu, sum, o);
        const float inv = 1.0f / sum;
#pragma unroll
        for (int q = 0; q < 8; q++)
            sp[r * NN + lane + 32 * q] = v[q] * inv;
    }
    __syncthreads();

    // Aggregation: acc[r] = sum_{j in half} p[r,j] * h[b,j,d]
    const int d    = t & (DD - 1);
    const int half = t >> 7;
    const float* hb = h + (size_t)b * NN * DD;
    {
        float acc[TI];
#pragma unroll
        for (int r = 0; r < TI; r++) acc[r] = 0.f;

        const int j0 = half * (NN / 2);
        for (int j = j0; j < j0 + NN / 2; j += 4) {
            const float hv0 = hb[(j + 0) * DD + d];
            const float hv1 = hb[(j + 1) * DD + d];
            const float hv2 = hb[(j + 2) * DD + d];
            const float hv3 = hb[(j + 3) * DD + d];
#pragma unroll
            for (int r = 0; r < TI; r++) {
                const float4 p = *(const float4*)&sp[r * NN + j];  // smem bcast
                acc[r] += p.x * hv0 + p.y * hv1 + p.z * hv2 + p.w * hv3;
            }
        }
#pragma unroll
        for (int r = 0; r < TI; r++)
            sagg[half * (TI * DD) + r * DD + d] = acc[r];
    }
    __syncthreads();

    // combine halves + add h (threads t<128)
    if (t < DD) {
#pragma unroll
        for (int r = 0; r < TI; r++)
            ss[r * DD + t] = sagg[r * DD + t] + sagg[TI * DD + r * DD + t]
                           + hb[(i0 + r) * DD + t];
    }
    __syncthreads();

    // Linear: y[r,k] = sum_{dd in half} s[r,dd] * W[k,dd]
    {
        const int k = d;
        float y[TI];
#pragma unroll
        for (int r = 0; r < TI; r++) y[r] = 0.f;

        const float* wrow  = W + (size_t)k * DD + half * (DD / 2);
        const float* sbase = ss + half * (DD / 2);
        for (int dd = 0; dd < DD / 2; dd += 4) {
            const float4 wv = *(const float4*)&wrow[dd];
#pragma unroll
            for (int r = 0; r < TI; r++) {
                const float4 sv = *(const float4*)&sbase[r * DD + dd];
                y[r] += sv.x * wv.x + sv.y * wv.y + sv.z * wv.z + sv.w * wv.w;
            }
        }
#pragma unroll
        for (int r = 0; r < TI; r++)
            sy[half * (TI * DD) + r * DD + k] = y[r];
    }
    __syncthreads();

    // ReLU + write + BN partials (threads t<128)
    if (t < DD) {
        const float bk = bias[t];
        float ps = 0.f, pq = 0.f;
#pragma unroll
        for (int r = 0; r < TI; r++) {
            const float v = fmaxf(sy[r * DD + t] + sy[TI * DD + r * DD + t] + bk, 0.f);
            g_x[(size_t)(gi0 + r) * DD + t] = v;
            ps += v;
            pq += v * v;
        }
        g_psum[t * NB + blk] = ps;
        g_psq [t * NB + blk] = pq;
    }
}

// ---------------------------------------------------------------------------
// K3: one block per channel; 256 threads reduce 512 block-partials
// (coalesced, channel-major), fold into scale+shift.
// ---------------------------------------------------------------------------
__global__ void __launch_bounds__(256) k3_bn_stats(
    const float* __restrict__ gamma, const float* __restrict__ beta)
{
    __shared__ float shs[256], shq[256];
    const int c = blockIdx.x;            // channel 0..127
    const int t = threadIdx.x;           // 0..255
    shs[t] = g_psum[c * NB + t] + g_psum[c * NB + t + 256];
    shq[t] = g_psq [c * NB + t] + g_psq [c * NB + t + 256];
    __syncthreads();
#pragma unroll
    for (int o = 128; o; o >>= 1) {
        if (t < o) { shs[t] += shs[t + o]; shq[t] += shq[t + o]; }
        __syncthreads();
    }
    if (t == 0) {
        const float inv_n = 1.0f / (float)ROWS;
        const float mean = shs[0] * inv_n;
        const float var  = shq[0] * inv_n - mean * mean;   // biased variance
        const float istd = rsqrtf(var + BN_EPS);
        const float sc   = gamma[c] * istd;
        g_scale[c] = sc;
        g_shift[c] = beta[c] - mean * sc;
    }
}

// ---------------------------------------------------------------------------
// K4: out_h = g_x * scale + shift + h   (float4, 65536 vec-elements)
// ---------------------------------------------------------------------------
__global__ void __launch_bounds__(256) k4_finalize(
    const float4* __restrict__ h4, float4* __restrict__ out4)
{
    const int i = blockIdx.x * blockDim.x + threadIdx.x;   // 0..65535
    const float4 x  = ((const float4*)g_x)[i];
    const float4 hv = h4[i];
    const int c = (i * 4) & (DD - 1);
    const float4 sc = *(const float4*)&g_scale[c];
    const float4 sh = *(const float4*)&g_shift[c];
    float4 o;
    o.x = x.x * sc.x + sh.x + hv.x;
    o.y = x.y * sc.y + sh.y + hv.y;
    o.z = x.z * sc.z + sh.z + hv.z;
    o.w = x.w * sc.w + sh.w + hv.w;
    out4[i] = o;
}

// ---------------------------------------------------------------------------
// Launch. Inputs (metadata order): h, e, W, b, gamma, beta.
// Output: [h_new (2048*128 f32)] ++ [e (8*256*256*128 f32)].
// ---------------------------------------------------------------------------
extern "C" void kernel_launch(void* const* d_in, const int* in_sizes, int n_in,
                              void* d_out, int out_size)
{
    const float* h     = (const float*)d_in[0];
    const float* e     = (const float*)d_in[1];
    const float* W     = (const float*)d_in[2];
    const float* bias  = (const float*)d_in[3];
    const float* gamma = (const float*)d_in[4];
    const float* beta  = (const float*)d_in[5];

    float* out_e = (float*)d_out + (size_t)ROWS * DD;

    // K1: 524288 edges / 8 per warp / 8 warps per block = 8192 blocks
    k1_norm_copy<<<NE / 8 / 8, 256>>>((const float4*)e, (float4*)out_e);

    // K2: 512 blocks x 256 threads
    k2_agg_linear<<<NB, 256>>>(h, W, bias);

    // K3: one block per channel
    k3_bn_stats<<<DD, 256>>>(gamma, beta);

    // K4: 65536 float4 / 256 = 256 blocks
    k4_finalize<<<ROWS * DD / 4 / 256, 256>>>((const float4*)h, (float4*)d_out);
}

// round 7
// speedup vs baseline: 1.1384x; 1.0042x over previous
#include <cuda_runtime.h>
#include <math.h>

// Problem constants (fixed shapes from reference)
#define BB 8
#define NN 256
#define DD 128
#define NE (BB*NN*NN)          // 524288 edges
#define ROWS (BB*NN)           // 2048
#define TI 4                   // rows per K2 block
#define NB (ROWS/TI)           // 512 K2 blocks
#define BN_EPS 1e-5f

// Scratch (static __device__ — no allocation)
__device__ float g_w[NE];            // edge softmax weights (2 MB)
__device__ float g_x[ROWS*DD];       // pre-BN linear+relu output (1 MB)
__device__ float g_psum[DD*NB];      // per-block BN partial sums (channel-major)
__device__ float g_psq[DD*NB];       // per-block BN partial sum-of-squares
__device__ float g_scale[DD];        // folded BN scale
__device__ float g_shift[DD];        // folded BN shift

// ---------------------------------------------------------------------------
// K1: per-edge L2 norm + passthrough copy of e. One warp = 16 edges,
// all 16 LDG.128 front-batched (8 KB in flight per warp), streaming hints,
// coalesced 64B norm writes from lanes 0-15. Memory-only kernel.
// ---------------------------------------------------------------------------
__global__ void __launch_bounds__(256) k1_norm_copy(
    const float4* __restrict__ e4, float4* __restrict__ oute4)
{
    const int warp  = (blockIdx.x * blockDim.x + threadIdx.x) >> 5;
    const int lane  = threadIdx.x & 31;
    const size_t edge0 = (size_t)warp * 16;          // 16 edges per warp

    float4 v[16];
#pragma unroll
    for (int k = 0; k < 16; k++)
        v[k] = __ldcs(&e4[(edge0 + k) * 32 + lane]);   // front-batched MLP=16
#pragma unroll
    for (int k = 0; k < 16; k++)
        __stcs(&oute4[(edge0 + k) * 32 + lane], v[k]);

    float s[16];
#pragma unroll
    for (int k = 0; k < 16; k++) {
        s[k] = v[k].x*v[k].x + v[k].y*v[k].y + v[k].z*v[k].z + v[k].w*v[k].w;
#pragma unroll
        for (int o = 16; o; o >>= 1)
            s[k] += __shfl_xor_sync(0xffffffffu, s[k], o);
    }
    // lane L (< 16) writes norm of edge L: coalesced 64B store per warp
    float mine = s[0];
#pragma unroll
    for (int k = 1; k < 16; k++)
        mine = (lane == k) ? s[k] : mine;
    if (lane < 16)
        g_w[edge0 + lane] = sqrtf(mine);
}

// ---------------------------------------------------------------------------
// K2: softmax + aggregation + linear (unchanged from R5 — measured ~4us).
// 512 blocks x 256 threads, TI=4 rows per block.
// ---------------------------------------------------------------------------
__global__ void __launch_bounds__(256) k2_agg_linear(
    const float* __restrict__ h, const float* __restrict__ W,
    const float* __restrict__ bias)
{
    __shared__ float sp [TI * NN];        // 4 KB: softmax probs
    __shared__ float sagg[2 * TI * DD];   // 4 KB: agg halves
    __shared__ float ss [TI * DD];        // 2 KB: h + agg
    __shared__ float sy [2 * TI * DD];    // 4 KB: linear halves

    const int t    = threadIdx.x;         // 0..255
    const int w    = t >> 5;              // warp 0..7
    const int lane = t & 31;
    const int blk  = blockIdx.x;          // 0..511
    const int gi0  = blk * TI;            // first global row
    const int b    = gi0 >> 8;            // batch
    const int i0   = gi0 & (NN - 1);      // local row within batch

    // Load 4 rows x 256 weights (coalesced: 1024 floats)
    const float* wsrc = g_w + (size_t)gi0 * NN;
#pragma unroll
    for (int k = 0; k < TI * NN / 256; k++)
        sp[t + 256 * k] = wsrc[t + 256 * k];
    __syncthreads();

    // Softmax: warp r handles row r
    if (w < TI) {
        const int r = w;
        float v[8];
        float m = -1e30f;
#pragma unroll
        for (int q = 0; q < 8; q++) {
            v[q] = sp[r * NN + lane + 32 * q];
            m = fmaxf(m, v[q]);
        }
#pragma unroll
        for (int o = 16; o; o >>= 1)
            m = fmaxf(m, __shfl_xor_sync(0xffffffffu, m, o));
        float sum = 0.f;
#pragma unroll
        for (int q = 0; q < 8; q++) { v[q] = __expf(v[q] - m); sum += v[q]; }
#pragma unroll
        for (int o = 16; o; o >>= 1)
            sum += __shfl_xor_sync(0xffffffffu, sum, o);
        const float inv = 1.0f / sum;
#pragma unroll
        for (int q = 0; q < 8; q++)
            sp[r * NN + lane + 32 * q] = v[q] * inv;
    }
    __syncthreads();

    // Aggregation: acc[r] = sum_{j in half} p[r,j] * h[b,j,d]
    const int d    = t & (DD - 1);
    const int half = t >> 7;
    const float* hb = h + (size_t)b * NN * DD;
    {
        float acc[TI];
#pragma unroll
        for (int r = 0; r < TI; r++) acc[r] = 0.f;

        const int j0 = half * (NN / 2);
        for (int j = j0; j < j0 + NN / 2; j += 4) {
            const float hv0 = hb[(j + 0) * DD + d];
            const float hv1 = hb[(j + 1) * DD + d];
            const float hv2 = hb[(j + 2) * DD + d];
            const float hv3 = hb[(j + 3) * DD + d];
#pragma unroll
            for (int r = 0; r < TI; r++) {
                const float4 p = *(const float4*)&sp[r * NN + j];  // smem bcast
                acc[r] += p.x * hv0 + p.y * hv1 + p.z * hv2 + p.w * hv3;
            }
        }
#pragma unroll
        for (int r = 0; r < TI; r++)
            sagg[half * (TI * DD) + r * DD + d] = acc[r];
    }
    __syncthreads();

    // combine halves + add h (threads t<128)
    if (t < DD) {
#pragma unroll
        for (int r = 0; r < TI; r++)
            ss[r * DD + t] = sagg[r * DD + t] + sagg[TI * DD + r * DD + t]
                           + hb[(i0 + r) * DD + t];
    }
    __syncthreads();

    // Linear: y[r,k] = sum_{dd in half} s[r,dd] * W[k,dd]
    {
        const int k = d;
        float y[TI];
#pragma unroll
        for (int r = 0; r < TI; r++) y[r] = 0.f;

        const float* wrow  = W + (size_t)k * DD + half * (DD / 2);
        const float* sbase = ss + half * (DD / 2);
        for (int dd = 0; dd < DD / 2; dd += 4) {
            const float4 wv = *(const float4*)&wrow[dd];
#pragma unroll
            for (int r = 0; r < TI; r++) {
                const float4 sv = *(const float4*)&sbase[r * DD + dd];
                y[r] += sv.x * wv.x + sv.y * wv.y + sv.z * wv.z + sv.w * wv.w;
            }
        }
#pragma unroll
        for (int r = 0; r < TI; r++)
            sy[half * (TI * DD) + r * DD + k] = y[r];
    }
    __syncthreads();

    // ReLU + write + BN partials (threads t<128)
    if (t < DD) {
        const float bk = bias[t];
        float ps = 0.f, pq = 0.f;
#pragma unroll
        for (int r = 0; r < TI; r++) {
            const float v = fmaxf(sy[r * DD + t] + sy[TI * DD + r * DD + t] + bk, 0.f);
            g_x[(size_t)(gi0 + r) * DD + t] = v;
            ps += v;
            pq += v * v;
        }
        g_psum[t * NB + blk] = ps;
        g_psq [t * NB + blk] = pq;
    }
}

// ---------------------------------------------------------------------------
// K3: one block per channel; 256 threads reduce 512 block-partials
// (coalesced, channel-major), fold into scale+shift.
// ---------------------------------------------------------------------------
__global__ void __launch_bounds__(256) k3_bn_stats(
    const float* __restrict__ gamma, const float* __restrict__ beta)
{
    __shared__ float shs[256], shq[256];
    const int c = blockIdx.x;            // channel 0..127
    const int t = threadIdx.x;           // 0..255
    shs[t] = g_psum[c * NB + t] + g_psum[c * NB + t + 256];
    shq[t] = g_psq [c * NB + t] + g_psq [c * NB + t + 256];
    __syncthreads();
#pragma unroll
    for (int o = 128; o; o >>= 1) {
        if (t < o) { shs[t] += shs[t + o]; shq[t] += shq[t + o]; }
        __syncthreads();
    }
    if (t == 0) {
        const float inv_n = 1.0f / (float)ROWS;
        const float mean = shs[0] * inv_n;
        const float var  = shq[0] * inv_n - mean * mean;   // biased variance
        const float istd = rsqrtf(var + BN_EPS);
        const float sc   = gamma[c] * istd;
        g_scale[c] = sc;
        g_shift[c] = beta[c] - mean * sc;
    }
}

// ---------------------------------------------------------------------------
// K4: out_h = g_x * scale + shift + h   (float4, 65536 vec-elements)
// ---------------------------------------------------------------------------
__global__ void __launch_bounds__(256) k4_finalize(
    const float4* __restrict__ h4, float4* __restrict__ out4)
{
    const int i = blockIdx.x * blockDim.x + threadIdx.x;   // 0..65535
    const float4 x  = ((const float4*)g_x)[i];
    const float4 hv = h4[i];
    const int c = (i * 4) & (DD - 1);
    const float4 sc = *(const float4*)&g_scale[c];
    const float4 sh = *(const float4*)&g_shift[c];
    float4 o;
    o.x = x.x * sc.x + sh.x + hv.x;
    o.y = x.y * sc.y + sh.y + hv.y;
    o.z = x.z * sc.z + sh.z + hv.z;
    o.w = x.w * sc.w + sh.w + hv.w;
    out4[i] = o;
}

// ---------------------------------------------------------------------------
// Launch. Inputs (metadata order): h, e, W, b, gamma, beta.
// Output: [h_new (2048*128 f32)] ++ [e (8*256*256*128 f32)].
// ---------------------------------------------------------------------------
extern "C" void kernel_launch(void* const* d_in, const int* in_sizes, int n_in,
                              void* d_out, int out_size)
{
    const float* h     = (const float*)d_in[0];
    const float* e     = (const float*)d_in[1];
    const float* W     = (const float*)d_in[2];
    const float* bias  = (const float*)d_in[3];
    const float* gamma = (const float*)d_in[4];
    const float* beta  = (const float*)d_in[5];

    float* out_e = (float*)d_out + (size_t)ROWS * DD;

    // K1: 524288 edges / 16 per warp / 8 warps per block = 4096 blocks
    k1_norm_copy<<<NE / 16 / 8, 256>>>((const float4*)e, (float4*)out_e);

    // K2: 512 blocks x 256 threads
    k2_agg_linear<<<NB, 256>>>(h, W, bias);

    // K3: one block per channel
    k3_bn_stats<<<DD, 256>>>(gamma, beta);

    // K4: 65536 float4 / 256 = 256 blocks
    k4_finalize<<<ROWS * DD / 4 / 256, 256>>>((const float4*)h, (float4*)d_out);
}